// round 13
// baseline (speedup 1.0000x reference)
#include <cuda_runtime.h>
#include <cuda_fp16.h>
#include <math.h>
#include <stdint.h>

// Problem constants
#define BB 4
#define LL 4096
#define DD 1024
#define HH 16
#define DH 64
#define MM 266
#define MP 272                 // M padded to 272 (34 n8-tiles)

#define NROWS (BB*LL)          // 16384
#define GROWS (BB*LL*HH)       // 262144
#define QK_SCALE 0.1767766952966369f   // 1/1024^0.25
#define PHI_SCALE 0.06131393394849658f // 1/sqrt(266)

// ---------------- scratch (device globals; no allocation allowed) -------------
__device__ __half g_qh[NROWS*DD];
__device__ __half g_kh[NROWS*DD];
__device__ __half g_vh[NROWS*DD];
__device__ __half g_wqh[DD*DD];
__device__ __half g_wkh[DD*DD];
__device__ __half g_wvh[DD*DD];
__device__ __half g_woh[DD*DD];
__device__ __half g_ctxh[NROWS*DD];
__device__ __half g_qprojh[NROWS*DD];
__device__ __half g_kprojh[NROWS*DD];
__device__ __half g_vprojh[NROWS*DD];
__device__ __half g_qp[(size_t)BB*HH*LL*MP];    // fp16 phi(q)
__device__ __half g_kp[(size_t)BB*HH*LL*MP];    // fp16 phi(k)
__device__ float g_kvpart[4*BB*HH*80*272];
__device__ __half g_kvT[BB*HH*80*272];          // fp16 kvT, row64=ksum

// ---------------- common helpers -----------------------------------------------
__device__ __forceinline__ void cp16(uint32_t s, const void* g) {
    asm volatile("cp.async.cg.shared.global [%0], [%1], 16;" :: "r"(s), "l"(g));
}
__device__ __forceinline__ void cp_commit() {
    asm volatile("cp.async.commit_group;");
}
template<int N> __device__ __forceinline__ void cp_wait() {
    asm volatile("cp.async.wait_group %0;" :: "n"(N));
}
__device__ __forceinline__ void mma_f16(float* c, const uint32_t* a, const uint32_t* b) {
    asm volatile(
        "mma.sync.aligned.m16n8k16.row.col.f32.f16.f16.f32 "
        "{%0,%1,%2,%3},{%4,%5,%6,%7},{%8,%9},{%0,%1,%2,%3};"
        : "+f"(c[0]), "+f"(c[1]), "+f"(c[2]), "+f"(c[3])
        : "r"(a[0]), "r"(a[1]), "r"(a[2]), "r"(a[3]), "r"(b[0]), "r"(b[1]));
}
__device__ __forceinline__ void ldsm_x4(uint32_t* d, uint32_t addr) {
    asm volatile("ldmatrix.sync.aligned.m8n8.x4.shared.b16 {%0,%1,%2,%3}, [%4];"
        : "=r"(d[0]), "=r"(d[1]), "=r"(d[2]), "=r"(d[3]) : "r"(addr));
}
__device__ __forceinline__ void ldsm_x2(uint32_t* d, uint32_t addr) {
    asm volatile("ldmatrix.sync.aligned.m8n8.x2.shared.b16 {%0,%1}, [%2];"
        : "=r"(d[0]), "=r"(d[1]) : "r"(addr));
}
__device__ __forceinline__ void ldsm_x2_t(uint32_t* d, uint32_t addr) {
    asm volatile("ldmatrix.sync.aligned.m8n8.x2.trans.shared.b16 {%0,%1}, [%2];"
        : "=r"(d[0]), "=r"(d[1]) : "r"(addr));
}

// ---------------- batched fp32 -> fp16 conversions ------------------------------
__global__ __launch_bounds__(256) void f2h3_kernel(
    const float4* __restrict__ s0, const float4* __restrict__ s1,
    const float4* __restrict__ s2, int n4)
{
    int i = blockIdx.x * 256 + threadIdx.x;
    if (i >= n4) return;
    const float4* src = (blockIdx.y == 0) ? s0 : (blockIdx.y == 1) ? s1 : s2;
    __half2* dst = (blockIdx.y == 0) ? (__half2*)g_qh
                 : (blockIdx.y == 1) ? (__half2*)g_kh : (__half2*)g_vh;
    float4 v = src[i];
    dst[2 * i + 0] = __floats2half2_rn(v.x, v.y);
    dst[2 * i + 1] = __floats2half2_rn(v.z, v.w);
}

__global__ __launch_bounds__(256) void f2h4_kernel(
    const float4* __restrict__ s0, const float4* __restrict__ s1,
    const float4* __restrict__ s2, const float4* __restrict__ s3, int n4)
{
    int i = blockIdx.x * 256 + threadIdx.x;
    if (i >= n4) return;
    const float4* src = (blockIdx.y == 0) ? s0 : (blockIdx.y == 1) ? s1
                      : (blockIdx.y == 2) ? s2 : s3;
    __half2* dst = (blockIdx.y == 0) ? (__half2*)g_wqh
                 : (blockIdx.y == 1) ? (__half2*)g_wkh
                 : (blockIdx.y == 2) ? (__half2*)g_wvh : (__half2*)g_woh;
    float4 v = src[i];
    dst[2 * i + 0] = __floats2half2_rn(v.x, v.y);
    dst[2 * i + 1] = __floats2half2_rn(v.z, v.w);
}

// ---------------- FP16 GEMM core (128x128 tile, BK=64, ldmatrix) ---------------
#define SHH 72

struct GemmOut {
    float2 o0, o1;
    int r0, c;
};

template <int OUT_FP16>
__device__ __forceinline__ void gemm_fp16_body(
    const __half* __restrict__ X, const __half* __restrict__ W,
    const float* __restrict__ bias, void* __restrict__ Yv,
    float alpha, int rowBase, int colBase, __half* hsm)
{
    __half* Abuf[2] = { hsm,                 hsm + 128 * SHH };
    __half* Bbuf[2] = { hsm + 2 * 128 * SHH, hsm + 3 * 128 * SHH };

    int tid = threadIdx.x;
    int lane = tid & 31, warp = tid >> 5;
    int wm = warp >> 2, wn = warp & 3;

    int lrow = tid >> 1, j0 = (tid & 1) * 4;
    const __half* gA = X + (size_t)(rowBase + lrow) * DD + j0 * 8;
    const __half* gB = W + (size_t)(colBase + lrow) * DD + j0 * 8;
    uint32_t sA[2][4], sB[2][4];
#pragma unroll
    for (int b = 0; b < 2; ++b)
#pragma unroll
        for (int i = 0; i < 4; ++i) {
            sA[b][i] = (uint32_t)__cvta_generic_to_shared(Abuf[b] + lrow * SHH + (j0 + i) * 8);
            sB[b][i] = (uint32_t)__cvta_generic_to_shared(Bbuf[b] + lrow * SHH + (j0 + i) * 8);
        }

#define LOAD_CHUNK(ch, b) do { \
    const __half* _ga = gA + (ch) * 64; \
    const __half* _gb = gB + (ch) * 64; \
    cp16(sA[b][0], _ga + 0);  cp16(sA[b][1], _ga + 8); \
    cp16(sA[b][2], _ga + 16); cp16(sA[b][3], _ga + 24); \
    cp16(sB[b][0], _gb + 0);  cp16(sB[b][1], _gb + 8); \
    cp16(sB[b][2], _gb + 16); cp16(sB[b][3], _gb + 24); \
    cp_commit(); \
} while (0)

    int jm = lane >> 3;
    int rowA = wm * 64 + (jm & 1) * 8 + (lane & 7);
    int colA = (jm >> 1) * 8;
    int l2 = lane & 15;
    int jb = l2 >> 3;
    int rowBn = wn * 32 + (l2 & 7);
    uint32_t aBase[2], bBase[2];
#pragma unroll
    for (int b = 0; b < 2; ++b) {
        aBase[b] = (uint32_t)__cvta_generic_to_shared(Abuf[b]) + 2 * (rowA * SHH + colA);
        bBase[b] = (uint32_t)__cvta_generic_to_shared(Bbuf[b]) + 2 * (rowBn * SHH + jb * 8);
    }

    float acc[4][4][4];
#pragma unroll
    for (int mt = 0; mt < 4; ++mt)
#pragma unroll
        for (int nt = 0; nt < 4; ++nt)
#pragma unroll
            for (int i = 0; i < 4; ++i) acc[mt][nt][i] = 0.f;

    LOAD_CHUNK(0, 0);

    int qd = lane & 3, r8 = lane >> 2;
    const int NCH = DD / 64;
    for (int kt = 0; kt < NCH; ++kt) {
        int buf = kt & 1;
        if (kt + 1 < NCH) {
            LOAD_CHUNK(kt + 1, buf ^ 1);
            cp_wait<1>();
        } else {
            cp_wait<0>();
        }
        __syncthreads();

#pragma unroll
        for (int ks = 0; ks < 4; ++ks) {
            uint32_t a[4][4], b[4][2];
#pragma unroll
            for (int mt = 0; mt < 4; ++mt)
                ldsm_x4(a[mt], aBase[buf] + 2 * (mt * 16 * SHH + ks * 16));
#pragma unroll
            for (int nt = 0; nt < 4; ++nt)
                ldsm_x2(b[nt], bBase[buf] + 2 * (nt * 8 * SHH + ks * 16));
#pragma unroll
            for (int mt = 0; mt < 4; ++mt)
#pragma unroll
                for (int nt = 0; nt < 4; ++nt)
                    mma_f16(acc[mt][nt], a[mt], b[nt]);
        }
        __syncthreads();
    }

#pragma unroll
    for (int mt = 0; mt < 4; ++mt) {
        int r0 = rowBase + wm * 64 + mt * 16 + r8;
#pragma unroll
        for (int nt = 0; nt < 4; ++nt) {
            int c = colBase + wn * 32 + nt * 8 + 2 * qd;
            float2 bv = *(const float2*)&bias[c];
            float2 o0, o1;
            o0.x = alpha * (acc[mt][nt][0] + bv.x);
            o0.y = alpha * (acc[mt][nt][1] + bv.y);
            o1.x = alpha * (acc[mt][nt][2] + bv.x);
            o1.y = alpha * (acc[mt][nt][3] + bv.y);
            if (OUT_FP16) {
                __half* Yh = (__half*)Yv;
                *(__half2*)&Yh[(size_t)r0 * DD + c]       = __floats2half2_rn(o0.x, o0.y);
                *(__half2*)&Yh[(size_t)(r0 + 8) * DD + c] = __floats2half2_rn(o1.x, o1.y);
            } else {
                float* Yf = (float*)Yv;
                *(float2*)&Yf[(size_t)r0 * DD + c] = o0;
                *(float2*)&Yf[(size_t)(r0 + 8) * DD + c] = o1;
            }
        }
    }
#undef LOAD_CHUNK
}

// batched q/k/v projection (grid.z selects)
__global__ __launch_bounds__(256) void gemm_proj_kernel(
    const float* __restrict__ q_b, const float* __restrict__ k_b,
    const float* __restrict__ v_b)
{
    extern __shared__ __align__(16) __half hsm[];
    int z = blockIdx.z;
    const __half* X = (z == 0) ? g_qh : (z == 1) ? g_kh : g_vh;
    const __half* W = (z == 0) ? g_wqh : (z == 1) ? g_wkh : g_wvh;
    const float* bias = (z == 0) ? q_b : (z == 1) ? k_b : v_b;
    __half* Y = (z == 0) ? g_qprojh : (z == 1) ? g_kprojh : g_vprojh;
    float alpha = (z == 2) ? 1.0f : QK_SCALE;
    gemm_fp16_body<1>(X, W, bias, Y, alpha,
                      blockIdx.y * 128, blockIdx.x * 128, hsm);
}

// final out projection (fp32 out)
__global__ __launch_bounds__(256) void gemm_out_kernel(
    const float* __restrict__ out_b, float* __restrict__ out)
{
    extern __shared__ __align__(16) __half hsm[];
    gemm_fp16_body<0>(g_ctxh, g_woh, out_b, out, 1.0f,
                      blockIdx.y * 128, blockIdx.x * 128, hsm);
}

// ---------------- phi: FP16 MMA + fused max/exp, occupancy-restructured --------
// grid (GROWS/64, 2): y=0 phi(qproj)->qp, y=1 phi(kproj)->kp. Block: 8 warps.
// warp w: half = w>>2 owns 17 n-tiles (136 cols), wg = w&3 owns 16 rows.
// Block covers 64 rows. Row-max combined across halves via smem.
__global__ __launch_bounds__(256, 2) void phi_gemm_kernel(
    const float* __restrict__ rf)
{
    extern __shared__ __half rfs[];   // [272][72]
    __shared__ float mxbuf[2][64];

    const __half* proj = blockIdx.y ? g_kprojh : g_qprojh;
    __half* out = blockIdx.y ? g_kp : g_qp;

    int tid = threadIdx.x;
    int lane = tid & 31, w = tid >> 5;
    int half = w >> 2, wg = w & 3;
    int g0 = blockIdx.x * 64;

    for (int idx = tid; idx < 266 * 16; idx += 256) {
        int m = idx >> 4, q = (idx & 15) * 4;
        float4 v = *(const float4*)&rf[m * 64 + q];
        *(__half2*)&rfs[m * 72 + q]     = __floats2half2_rn(v.x, v.y);
        *(__half2*)&rfs[m * 72 + q + 2] = __floats2half2_rn(v.z, v.w);
    }
    for (int idx = tid; idx < 6 * 64; idx += 256) {
        int m = 266 + idx / 64, d = idx % 64;
        rfs[m * 72 + d] = __ushort_as_half((unsigned short)0);
    }

    int c = lane & 3, r = lane >> 2;
    int arow = wg * 16 + r;                // 0..63 within block
    int row0 = g0 + arow, row1 = row0 + 8;

    uint32_t x0h[8], x1h[8];
    const __half* p0 = proj + (size_t)row0 * 64;
    const __half* p1 = proj + (size_t)row1 * 64;
#pragma unroll
    for (int ks = 0; ks < 4; ++ks) {
        x0h[2 * ks]     = *(const uint32_t*)(p0 + ks * 16 + 2 * c);
        x0h[2 * ks + 1] = *(const uint32_t*)(p0 + ks * 16 + 8 + 2 * c);
        x1h[2 * ks]     = *(const uint32_t*)(p1 + ks * 16 + 2 * c);
        x1h[2 * ks + 1] = *(const uint32_t*)(p1 + ks * 16 + 8 + 2 * c);
    }

    float s0 = 0.f, s1 = 0.f;
#pragma unroll
    for (int j = 0; j < 8; ++j) {
        float2 f0 = __half22float2(*(const __half2*)&x0h[j]);
        float2 f1 = __half22float2(*(const __half2*)&x1h[j]);
        s0 += f0.x * f0.x + f0.y * f0.y;
        s1 += f1.x * f1.x + f1.y * f1.y;
    }
    s0 += __shfl_xor_sync(0xffffffffu, s0, 1);
    s0 += __shfl_xor_sync(0xffffffffu, s0, 2);
    s1 += __shfl_xor_sync(0xffffffffu, s1, 1);
    s1 += __shfl_xor_sync(0xffffffffu, s1, 2);
    float h0 = -0.5f * s0, h1 = -0.5f * s1;

    __syncthreads();

    float acc[17][4];
#pragma unroll
    for (int t = 0; t < 17; ++t)
#pragma unroll
        for (int i = 0; i < 4; ++i) acc[t][i] = 0.f;

#pragma unroll
    for (int ks = 0; ks < 4; ++ks) {
        uint32_t a[4];
        a[0] = x0h[2 * ks];
        a[1] = x1h[2 * ks];
        a[2] = x0h[2 * ks + 1];
        a[3] = x1h[2 * ks + 1];
#pragma unroll
        for (int tt = 0; tt < 17; ++tt) {
            int br = (half * 17 + tt) * 8 + r;
            uint32_t b[2];
            b[0] = *(const uint32_t*)(rfs + br * 72 + ks * 16 + 2 * c);
            b[1] = *(const uint32_t*)(rfs + br * 72 + ks * 16 + 8 + 2 * c);
            mma_f16(acc[tt], a, b);
        }
    }

    // local max over this half's tiles
    float mx0 = -3.0e38f, mx1 = -3.0e38f;
#pragma unroll
    for (int tt = 0; tt < 17; ++tt) {
        int c0 = (half * 17 + tt) * 8 + 2 * c;
        if (c0 < 266)     { mx0 = fmaxf(mx0, acc[tt][0]); mx1 = fmaxf(mx1, acc[tt][2]); }
        if (c0 + 1 < 266) { mx0 = fmaxf(mx0, acc[tt][1]); mx1 = fmaxf(mx1, acc[tt][3]); }
    }
    mx0 = fmaxf(mx0, __shfl_xor_sync(0xffffffffu, mx0, 1));
    mx0 = fmaxf(mx0, __shfl_xor_sync(0xffffffffu, mx0, 2));
    mx1 = fmaxf(mx1, __shfl_xor_sync(0xffffffffu, mx1, 1));
    mx1 = fmaxf(mx1, __shfl_xor_sync(0xffffffffu, mx1, 2));

    if (c == 0) {
        mxbuf[half][arow]     = mx0;
        mxbuf[half][arow + 8] = mx1;
    }
    __syncthreads();
    mx0 = fmaxf(mxbuf[0][arow],     mxbuf[1][arow]);
    mx1 = fmaxf(mxbuf[0][arow + 8], mxbuf[1][arow + 8]);

    int b0i = row0 >> 16, rem0 = row0 & 65535, l0 = rem0 >> 4, hh0 = rem0 & 15;
    int b1i = row1 >> 16, rem1 = row1 & 65535, l1 = rem1 >> 4, hh1 = rem1 & 15;
    __half* d0p = out + ((size_t)(b0i * 16 + hh0) * LL + l0) * MP;
    __half* d1p = out + ((size_t)(b1i * 16 + hh1) * LL + l1) * MP;

#pragma unroll
    for (int tt = 0; tt < 17; ++tt) {
        int c0 = (half * 17 + tt) * 8 + 2 * c;
        float v0x = (c0     < 266) ? __expf(h0 + acc[tt][0] - mx0) * PHI_SCALE : 0.f;
        float v0y = (c0 + 1 < 266) ? __expf(h0 + acc[tt][1] - mx0) * PHI_SCALE : 0.f;
        float v1x = (c0     < 266) ? __expf(h1 + acc[tt][2] - mx1) * PHI_SCALE : 0.f;
        float v1y = (c0 + 1 < 266) ? __expf(h1 + acc[tt][3] - mx1) * PHI_SCALE : 0.f;
        *(__half2*)&d0p[c0] = __floats2half2_rn(v0x, v0y);
        *(__half2*)&d1p[c0] = __floats2half2_rn(v1x, v1y);
    }
}

// ---------------- kv as FP16 MMA: kvT[d][m] = sum_l vT[d][l]*kp[l][m] ----------
__global__ __launch_bounds__(256) void kv_gemm_kernel(float* __restrict__ kvpart)
{
    __shared__ __align__(16) __half kps[32 * 280];
    __shared__ __align__(16) __half vsT[80 * 40];

    int tid = threadIdx.x;
    int lane = tid & 31, w = tid >> 5;
    int split = blockIdx.x, bh = blockIdx.y;
    int b = bh >> 4, h = bh & 15;
    int c = lane & 3, r = lane >> 2;

    for (int idx = tid; idx < 16 * 40; idx += 256) {
        int rr = idx / 40, l = idx % 40;
        vsT[(64 + rr) * 40 + l] = (rr == 0) ? __float2half(1.0f)
                                            : __ushort_as_half((unsigned short)0);
    }

    int lrow_ldsm = (lane & 7) + ((lane & 8) ? 8 : 0);
    uint32_t kpsBase = (uint32_t)__cvta_generic_to_shared(kps) + 2 * (lrow_ldsm * 280);

    int ntiles = (w < 2) ? 5 : 4;
    float acc[5][5][4];
#pragma unroll
    for (int mt = 0; mt < 5; ++mt)
#pragma unroll
        for (int j = 0; j < 5; ++j)
#pragma unroll
            for (int i = 0; i < 4; ++i) acc[mt][j][i] = 0.f;

    int lbase = split * 1024;
    for (int ch = 0; ch < 32; ++ch) {
        int l0 = lbase + ch * 32;
        __syncthreads();
        for (int idx = tid; idx < 32 * 34; idx += 256) {
            int l = idx / 34, m8 = idx % 34;
            *(float4*)&kps[l * 280 + m8 * 8] =
                *(const float4*)&g_kp[((size_t)bh * LL + l0 + l) * MP + m8 * 8];
        }
        for (int idx = tid; idx < 32 * 32; idx += 256) {
            int l = idx >> 5, d2 = idx & 31;
            __half2 v = *(const __half2*)&g_vprojh[((size_t)(b * LL + l0 + l)) * DD + h * DH + 2 * d2];
            vsT[(2 * d2 + 0) * 40 + l] = __low2half(v);
            vsT[(2 * d2 + 1) * 40 + l] = __high2half(v);
        }
        __syncthreads();

#pragma unroll
        for (int ks = 0; ks < 2; ++ks) {
            uint32_t a[5][4];
#pragma unroll
            for (int mt = 0; mt < 5; ++mt) {
                int ar = mt * 16 + r;
                a[mt][0] = *(const uint32_t*)(vsT + ar * 40 + ks * 16 + 2 * c);
                a[mt][1] = *(const uint32_t*)(vsT + (ar + 8) * 40 + ks * 16 + 2 * c);
                a[mt][2] = *(const uint32_t*)(vsT + ar * 40 + ks * 16 + 8 + 2 * c);
                a[mt][3] = *(const uint32_t*)(vsT + (ar + 8) * 40 + ks * 16 + 8 + 2 * c);
            }
#pragma unroll
            for (int j = 0; j < 5; ++j) {
                if (j >= ntiles) break;
                int t = (j < 4) ? (w + 8 * j) : (32 + w);
                uint32_t bfr[2];
                ldsm_x2_t(bfr, kpsBase + 2 * (ks * 16 * 280 + t * 8));
#pragma unroll
                for (int mt = 0; mt < 5; ++mt)
                    mma_f16(acc[mt][j], a[mt], bfr);
            }
        }
    }

    float* dst = kvpart + (size_t)(split * 64 + bh) * 80 * 272;
#pragma unroll
    for (int mt = 0; mt < 5; ++mt) {
        int d0 = mt * 16 + r;
#pragma unroll
        for (int j = 0; j < 5; ++j) {
            if (j >= ntiles) break;
            int t = (j < 4) ? (w + 8 * j) : (32 + w);
            int cc = t * 8 + 2 * c;
            *(float2*)&dst[d0 * 272 + cc]       = make_float2(acc[mt][j][0], acc[mt][j][1]);
            *(float2*)&dst[(d0 + 8) * 272 + cc] = make_float2(acc[mt][j][2], acc[mt][j][3]);
        }
    }
}

__global__ __launch_bounds__(256) void kv_reduce_kernel(
    const float* __restrict__ kvpart)
{
    int idx = blockIdx.x * 256 + threadIdx.x;
    const int total = 64 * 80 * 272;
    if (idx < total) {
        float s = kvpart[idx] + kvpart[total + idx]
                + kvpart[2 * total + idx] + kvpart[3 * total + idx];
        g_kvT[idx] = __float2half_rn(s);
    }
}

// ---------------- ctx as FP16 MMA with fused denom -> fp16 out ------------------
__global__ __launch_bounds__(256) void ctx_gemm_kernel()
{
    extern __shared__ __align__(16) __half csm[];
    __half* kvs = csm;               // [80][280]
    __half* As  = csm + 80 * 280;    // [128][24]

    int tid = threadIdx.x;
    int lane = tid & 31, w = tid >> 5;
    int bh = blockIdx.y;
    int b = bh >> 4, h = bh & 15;
    int lblk = blockIdx.x * 128;
    int c = lane & 3, r = lane >> 2;

    for (int idx = tid; idx < 80 * 34; idx += 256) {
        int d = idx / 34, q = idx % 34;
        *(float4*)&kvs[d * 280 + q * 8] =
            *(const float4*)&g_kvT[(size_t)bh * 80 * 272 + d * 272 + q * 8];
    }

    float acc[9][4];
#pragma unroll
    for (int t = 0; t < 9; ++t)
#pragma unroll
        for (int i = 0; i < 4; ++i) acc[t][i] = 0.f;

    int arow = w * 16 + r;

    for (int ch = 0; ch < 17; ++ch) {
        __syncthreads();
        {
            int rr = tid >> 1, part = tid & 1;
            *(float4*)&As[rr * 24 + part * 8] =
                *(const float4*)&g_qp[((size_t)bh * LL + lblk + rr) * MP + ch * 16 + part * 8];
        }
        __syncthreads();

        uint32_t a[4];
        a[0] = *(const uint32_t*)(As + arow * 24 + 2 * c);
        a[1] = *(const uint32_t*)(As + (arow + 8) * 24 + 2 * c);
        a[2] = *(const uint32_t*)(As + arow * 24 + 8 + 2 * c);
        a[3] = *(const uint32_t*)(As + (arow + 8) * 24 + 8 + 2 * c);
#pragma unroll
        for (int t = 0; t < 9; ++t) {
            int br = t * 8 + r;
            uint32_t bfr[2];
            bfr[0] = *(const uint32_t*)(kvs + br * 280 + ch * 16 + 2 * c);
            bfr[1] = *(const uint32_t*)(kvs + br * 280 + ch * 16 + 8 + 2 * c);
            mma_f16(acc[t], a, bfr);
        }
    }

    float den0 = __shfl_sync(0xffffffffu, acc[8][0], lane & ~3);
    float den1 = __shfl_sync(0xffffffffu, acc[8][2], lane & ~3);
    float inv0 = 1.0f / (den0 + 1e-6f);
    float inv1 = 1.0f / (den1 + 1e-6f);

    int lrow0 = lblk + arow, lrow1 = lblk + arow + 8;
    __half* o0 = g_ctxh + ((size_t)(b * LL + lrow0)) * DD + h * DH;
    __half* o1 = g_ctxh + ((size_t)(b * LL + lrow1)) * DD + h * DH;
#pragma unroll
    for (int t = 0; t < 8; ++t) {
        int cc = t * 8 + 2 * c;
        *(__half2*)&o0[cc] = __floats2half2_rn(acc[t][0] * inv0, acc[t][1] * inv0);
        *(__half2*)&o1[cc] = __floats2half2_rn(acc[t][2] * inv1, acc[t][3] * inv1);
    }
}

// ---------------- host launcher ------------------------------------------------
extern "C" void kernel_launch(void* const* d_in, const int* in_sizes, int n_in,
                              void* d_out, int out_size)
{
    const float* query = (const float*)d_in[0];
    const float* key   = (const float*)d_in[1];
    const float* value = (const float*)d_in[2];
    const float* q_w   = (const float*)d_in[3];
    const float* q_b   = (const float*)d_in[4];
    const float* k_w   = (const float*)d_in[5];
    const float* k_b   = (const float*)d_in[6];
    const float* v_w   = (const float*)d_in[7];
    const float* v_b   = (const float*)d_in[8];
    const float* out_w = (const float*)d_in[9];
    const float* out_b = (const float*)d_in[10];
    const float* rf    = (const float*)d_in[11];
    float* out = (float*)d_out;

    float* p_kvpart;
    cudaGetSymbolAddress((void**)&p_kvpart, g_kvpart);

    int gemm_smem = 4 * 128 * SHH * sizeof(__half);            // 73,728 B
    int phi_smem  = 272 * 72 * sizeof(__half);                 // 39,168 B
    int ctx_smem  = (80 * 280 + 128 * 24) * sizeof(__half);    // 50,944 B
    cudaFuncSetAttribute(gemm_proj_kernel, cudaFuncAttributeMaxDynamicSharedMemorySize, gemm_smem);
    cudaFuncSetAttribute(gemm_out_kernel,  cudaFuncAttributeMaxDynamicSharedMemorySize, gemm_smem);
    cudaFuncSetAttribute(phi_gemm_kernel,  cudaFuncAttributeMaxDynamicSharedMemorySize, phi_smem);
    cudaFuncSetAttribute(ctx_gemm_kernel,  cudaFuncAttributeMaxDynamicSharedMemorySize, ctx_smem);

    const int NB = NROWS * DD / 4;
    const int WB = DD * DD / 4;

    dim3 f3Grid((NB + 255) / 256, 3);
    f2h3_kernel<<<f3Grid, 256>>>((const float4*)query, (const float4*)key,
                                 (const float4*)value, NB);
    dim3 f4Grid((WB + 255) / 256, 4);
    f2h4_kernel<<<f4Grid, 256>>>((const float4*)q_w, (const float4*)k_w,
                                 (const float4*)v_w, (const float4*)out_w, WB);

    dim3 projGrid(DD / 128, NROWS / 128, 3);   // (8, 128, 3)
    gemm_proj_kernel<<<projGrid, 256, gemm_smem>>>(q_b, k_b, v_b);

    dim3 phiGrid(GROWS / 64, 2);               // (4096, 2)
    phi_gemm_kernel<<<phiGrid, 256, phi_smem>>>(rf);

    dim3 kvGrid(4, BB * HH);
    kv_gemm_kernel<<<kvGrid, 256>>>(p_kvpart);
    kv_reduce_kernel<<<(64 * 80 * 272 + 255) / 256, 256>>>(p_kvpart);

    dim3 ctxGrid(LL / 128, BB * HH);
    ctx_gemm_kernel<<<ctxGrid, 256, ctx_smem>>>();

    dim3 outGrid(DD / 128, NROWS / 128);
    gemm_out_kernel<<<outGrid, 256, gemm_smem>>>(out_b, out);
}

// round 17
// speedup vs baseline: 1.0220x; 1.0220x over previous
#include <cuda_runtime.h>
#include <cuda_fp16.h>
#include <math.h>
#include <stdint.h>

// Problem constants
#define BB 4
#define LL 4096
#define DD 1024
#define HH 16
#define DH 64
#define MM 266
#define MP 272                 // M padded to 272 (34 n8-tiles)

#define NROWS (BB*LL)          // 16384
#define GROWS (BB*LL*HH)       // 262144
#define QK_SCALE 0.1767766952966369f   // 1/1024^0.25
#define PHI_SCALE 0.06131393394849658f // 1/sqrt(266)

// ---------------- scratch (device globals; no allocation allowed) -------------
__device__ __half g_qh[NROWS*DD];
__device__ __half g_kh[NROWS*DD];
__device__ __half g_vh[NROWS*DD];
__device__ __half g_wqh[DD*DD];
__device__ __half g_wkh[DD*DD];
__device__ __half g_wvh[DD*DD];
__device__ __half g_woh[DD*DD];
__device__ __half g_ctxh[NROWS*DD];
__device__ __half g_qprojh[NROWS*DD];
__device__ __half g_kprojh[NROWS*DD];
__device__ __half g_vprojh[NROWS*DD];
__device__ __half g_qp[(size_t)BB*HH*LL*MP];    // fp16 phi(q)
__device__ __half g_kp[(size_t)BB*HH*LL*MP];    // fp16 phi(k)
__device__ float g_kvpart[4*BB*HH*80*272];
__device__ __half g_kvT[BB*HH*80*272];          // fp16 kvT, row64=ksum

// ---------------- common helpers -----------------------------------------------
__device__ __forceinline__ void cp16(uint32_t s, const void* g) {
    asm volatile("cp.async.cg.shared.global [%0], [%1], 16;" :: "r"(s), "l"(g));
}
__device__ __forceinline__ void cp_commit() {
    asm volatile("cp.async.commit_group;");
}
template<int N> __device__ __forceinline__ void cp_wait() {
    asm volatile("cp.async.wait_group %0;" :: "n"(N));
}
__device__ __forceinline__ void mma_f16(float* c, const uint32_t* a, const uint32_t* b) {
    asm volatile(
        "mma.sync.aligned.m16n8k16.row.col.f32.f16.f16.f32 "
        "{%0,%1,%2,%3},{%4,%5,%6,%7},{%8,%9},{%0,%1,%2,%3};"
        : "+f"(c[0]), "+f"(c[1]), "+f"(c[2]), "+f"(c[3])
        : "r"(a[0]), "r"(a[1]), "r"(a[2]), "r"(a[3]), "r"(b[0]), "r"(b[1]));
}
__device__ __forceinline__ void ldsm_x4(uint32_t* d, uint32_t addr) {
    asm volatile("ldmatrix.sync.aligned.m8n8.x4.shared.b16 {%0,%1,%2,%3}, [%4];"
        : "=r"(d[0]), "=r"(d[1]), "=r"(d[2]), "=r"(d[3]) : "r"(addr));
}
__device__ __forceinline__ void ldsm_x2(uint32_t* d, uint32_t addr) {
    asm volatile("ldmatrix.sync.aligned.m8n8.x2.shared.b16 {%0,%1}, [%2];"
        : "=r"(d[0]), "=r"(d[1]) : "r"(addr));
}
__device__ __forceinline__ void ldsm_x2_t(uint32_t* d, uint32_t addr) {
    asm volatile("ldmatrix.sync.aligned.m8n8.x2.trans.shared.b16 {%0,%1}, [%2];"
        : "=r"(d[0]), "=r"(d[1]) : "r"(addr));
}

// ---------------- batched fp32 -> fp16 conversions ------------------------------
__global__ __launch_bounds__(256) void f2h3_kernel(
    const float4* __restrict__ s0, const float4* __restrict__ s1,
    const float4* __restrict__ s2, int n4)
{
    int i = blockIdx.x * 256 + threadIdx.x;
    if (i >= n4) return;
    const float4* src = (blockIdx.y == 0) ? s0 : (blockIdx.y == 1) ? s1 : s2;
    __half2* dst = (blockIdx.y == 0) ? (__half2*)g_qh
                 : (blockIdx.y == 1) ? (__half2*)g_kh : (__half2*)g_vh;
    float4 v = src[i];
    dst[2 * i + 0] = __floats2half2_rn(v.x, v.y);
    dst[2 * i + 1] = __floats2half2_rn(v.z, v.w);
}

__global__ __launch_bounds__(256) void f2h4_kernel(
    const float4* __restrict__ s0, const float4* __restrict__ s1,
    const float4* __restrict__ s2, const float4* __restrict__ s3, int n4)
{
    int i = blockIdx.x * 256 + threadIdx.x;
    if (i >= n4) return;
    const float4* src = (blockIdx.y == 0) ? s0 : (blockIdx.y == 1) ? s1
                      : (blockIdx.y == 2) ? s2 : s3;
    __half2* dst = (blockIdx.y == 0) ? (__half2*)g_wqh
                 : (blockIdx.y == 1) ? (__half2*)g_wkh
                 : (blockIdx.y == 2) ? (__half2*)g_wvh : (__half2*)g_woh;
    float4 v = src[i];
    dst[2 * i + 0] = __floats2half2_rn(v.x, v.y);
    dst[2 * i + 1] = __floats2half2_rn(v.z, v.w);
}

// ---------------- FP16 GEMM core (128x128 tile, BK=64, ldmatrix) ---------------
#define SHH 72

template <int OUT_FP16>
__device__ __forceinline__ void gemm_fp16_body(
    const __half* __restrict__ X, const __half* __restrict__ W,
    const float* __restrict__ bias, void* __restrict__ Yv,
    float alpha, int rowBase, int colBase, __half* hsm)
{
    __half* Abuf[2] = { hsm,                 hsm + 128 * SHH };
    __half* Bbuf[2] = { hsm + 2 * 128 * SHH, hsm + 3 * 128 * SHH };

    int tid = threadIdx.x;
    int lane = tid & 31, warp = tid >> 5;
    int wm = warp >> 2, wn = warp & 3;

    int lrow = tid >> 1, j0 = (tid & 1) * 4;
    const __half* gA = X + (size_t)(rowBase + lrow) * DD + j0 * 8;
    const __half* gB = W + (size_t)(colBase + lrow) * DD + j0 * 8;
    uint32_t sA[2][4], sB[2][4];
#pragma unroll
    for (int b = 0; b < 2; ++b)
#pragma unroll
        for (int i = 0; i < 4; ++i) {
            sA[b][i] = (uint32_t)__cvta_generic_to_shared(Abuf[b] + lrow * SHH + (j0 + i) * 8);
            sB[b][i] = (uint32_t)__cvta_generic_to_shared(Bbuf[b] + lrow * SHH + (j0 + i) * 8);
        }

#define LOAD_CHUNK(ch, b) do { \
    const __half* _ga = gA + (ch) * 64; \
    const __half* _gb = gB + (ch) * 64; \
    cp16(sA[b][0], _ga + 0);  cp16(sA[b][1], _ga + 8); \
    cp16(sA[b][2], _ga + 16); cp16(sA[b][3], _ga + 24); \
    cp16(sB[b][0], _gb + 0);  cp16(sB[b][1], _gb + 8); \
    cp16(sB[b][2], _gb + 16); cp16(sB[b][3], _gb + 24); \
    cp_commit(); \
} while (0)

    int jm = lane >> 3;
    int rowA = wm * 64 + (jm & 1) * 8 + (lane & 7);
    int colA = (jm >> 1) * 8;
    int l2 = lane & 15;
    int jb = l2 >> 3;
    int rowBn = wn * 32 + (l2 & 7);
    uint32_t aBase[2], bBase[2];
#pragma unroll
    for (int b = 0; b < 2; ++b) {
        aBase[b] = (uint32_t)__cvta_generic_to_shared(Abuf[b]) + 2 * (rowA * SHH + colA);
        bBase[b] = (uint32_t)__cvta_generic_to_shared(Bbuf[b]) + 2 * (rowBn * SHH + jb * 8);
    }

    float acc[4][4][4];
#pragma unroll
    for (int mt = 0; mt < 4; ++mt)
#pragma unroll
        for (int nt = 0; nt < 4; ++nt)
#pragma unroll
            for (int i = 0; i < 4; ++i) acc[mt][nt][i] = 0.f;

    LOAD_CHUNK(0, 0);

    int qd = lane & 3, r8 = lane >> 2;
    const int NCH = DD / 64;
    for (int kt = 0; kt < NCH; ++kt) {
        int buf = kt & 1;
        if (kt + 1 < NCH) {
            LOAD_CHUNK(kt + 1, buf ^ 1);
            cp_wait<1>();
        } else {
            cp_wait<0>();
        }
        __syncthreads();

#pragma unroll
        for (int ks = 0; ks < 4; ++ks) {
            uint32_t a[4][4], b[4][2];
#pragma unroll
            for (int mt = 0; mt < 4; ++mt)
                ldsm_x4(a[mt], aBase[buf] + 2 * (mt * 16 * SHH + ks * 16));
#pragma unroll
            for (int nt = 0; nt < 4; ++nt)
                ldsm_x2(b[nt], bBase[buf] + 2 * (nt * 8 * SHH + ks * 16));
#pragma unroll
            for (int mt = 0; mt < 4; ++mt)
#pragma unroll
                for (int nt = 0; nt < 4; ++nt)
                    mma_f16(acc[mt][nt], a[mt], b[nt]);
        }
        __syncthreads();
    }

#pragma unroll
    for (int mt = 0; mt < 4; ++mt) {
        int r0 = rowBase + wm * 64 + mt * 16 + r8;
#pragma unroll
        for (int nt = 0; nt < 4; ++nt) {
            int c = colBase + wn * 32 + nt * 8 + 2 * qd;
            float2 bv = *(const float2*)&bias[c];
            float2 o0, o1;
            o0.x = alpha * (acc[mt][nt][0] + bv.x);
            o0.y = alpha * (acc[mt][nt][1] + bv.y);
            o1.x = alpha * (acc[mt][nt][2] + bv.x);
            o1.y = alpha * (acc[mt][nt][3] + bv.y);
            if (OUT_FP16) {
                __half* Yh = (__half*)Yv;
                *(__half2*)&Yh[(size_t)r0 * DD + c]       = __floats2half2_rn(o0.x, o0.y);
                *(__half2*)&Yh[(size_t)(r0 + 8) * DD + c] = __floats2half2_rn(o1.x, o1.y);
            } else {
                float* Yf = (float*)Yv;
                *(float2*)&Yf[(size_t)r0 * DD + c] = o0;
                *(float2*)&Yf[(size_t)(r0 + 8) * DD + c] = o1;
            }
        }
    }
#undef LOAD_CHUNK
}

// batched q/k/v projection (grid.z selects)
__global__ __launch_bounds__(256) void gemm_proj_kernel(
    const float* __restrict__ q_b, const float* __restrict__ k_b,
    const float* __restrict__ v_b)
{
    extern __shared__ __align__(16) __half hsm[];
    int z = blockIdx.z;
    const __half* X = (z == 0) ? g_qh : (z == 1) ? g_kh : g_vh;
    const __half* W = (z == 0) ? g_wqh : (z == 1) ? g_wkh : g_wvh;
    const float* bias = (z == 0) ? q_b : (z == 1) ? k_b : v_b;
    __half* Y = (z == 0) ? g_qprojh : (z == 1) ? g_kprojh : g_vprojh;
    float alpha = (z == 2) ? 1.0f : QK_SCALE;
    gemm_fp16_body<1>(X, W, bias, Y, alpha,
                      blockIdx.y * 128, blockIdx.x * 128, hsm);
}

// final out projection (fp32 out)
__global__ __launch_bounds__(256) void gemm_out_kernel(
    const float* __restrict__ out_b, float* __restrict__ out)
{
    extern __shared__ __align__(16) __half hsm[];
    gemm_fp16_body<0>(g_ctxh, g_woh, out_b, out, 1.0f,
                      blockIdx.y * 128, blockIdx.x * 128, hsm);
}

// ---------------- phi: FP16 MMA + fused max/exp (R12 body, batched q/k) --------
// grid (GROWS/128, 2): y=0 phi(qproj)->qp, y=1 phi(kproj)->kp. 8 warps, 128 rows.
__global__ __launch_bounds__(256) void phi_gemm_kernel(const float* __restrict__ rf)
{
    extern __shared__ __half rfs[];   // [272][72]

    const __half* proj = blockIdx.y ? g_kprojh : g_qprojh;
    __half* out = blockIdx.y ? g_kp : g_qp;

    int tid = threadIdx.x;
    int lane = tid & 31, w = tid >> 5;
    int g0 = blockIdx.x * 128;

    for (int idx = tid; idx < 266 * 16; idx += 256) {
        int m = idx >> 4, q = (idx & 15) * 4;
        float4 v = *(const float4*)&rf[m * 64 + q];
        *(__half2*)&rfs[m * 72 + q]     = __floats2half2_rn(v.x, v.y);
        *(__half2*)&rfs[m * 72 + q + 2] = __floats2half2_rn(v.z, v.w);
    }
    for (int idx = tid; idx < 6 * 64; idx += 256) {
        int m = 266 + idx / 64, d = idx % 64;
        rfs[m * 72 + d] = __ushort_as_half((unsigned short)0);
    }

    int c = lane & 3, r = lane >> 2;
    int arow = w * 16 + r;
    int row0 = g0 + arow, row1 = row0 + 8;

    uint32_t x0h[8], x1h[8];
    const __half* p0 = proj + (size_t)row0 * 64;
    const __half* p1 = proj + (size_t)row1 * 64;
#pragma unroll
    for (int ks = 0; ks < 4; ++ks) {
        x0h[2 * ks]     = *(const uint32_t*)(p0 + ks * 16 + 2 * c);
        x0h[2 * ks + 1] = *(const uint32_t*)(p0 + ks * 16 + 8 + 2 * c);
        x1h[2 * ks]     = *(const uint32_t*)(p1 + ks * 16 + 2 * c);
        x1h[2 * ks + 1] = *(const uint32_t*)(p1 + ks * 16 + 8 + 2 * c);
    }

    float s0 = 0.f, s1 = 0.f;
#pragma unroll
    for (int j = 0; j < 8; ++j) {
        float2 f0 = __half22float2(*(const __half2*)&x0h[j]);
        float2 f1 = __half22float2(*(const __half2*)&x1h[j]);
        s0 += f0.x * f0.x + f0.y * f0.y;
        s1 += f1.x * f1.x + f1.y * f1.y;
    }
    s0 += __shfl_xor_sync(0xffffffffu, s0, 1);
    s0 += __shfl_xor_sync(0xffffffffu, s0, 2);
    s1 += __shfl_xor_sync(0xffffffffu, s1, 1);
    s1 += __shfl_xor_sync(0xffffffffu, s1, 2);
    float h0 = -0.5f * s0, h1 = -0.5f * s1;

    __syncthreads();

    float acc[34][4];
#pragma unroll
    for (int t = 0; t < 34; ++t)
#pragma unroll
        for (int i = 0; i < 4; ++i) acc[t][i] = 0.f;

#pragma unroll
    for (int ks = 0; ks < 4; ++ks) {
        uint32_t a[4];
        a[0] = x0h[2 * ks];
        a[1] = x1h[2 * ks];
        a[2] = x0h[2 * ks + 1];
        a[3] = x1h[2 * ks + 1];
#pragma unroll
        for (int t = 0; t < 34; ++t) {
            int br = t * 8 + r;
            uint32_t b[2];
            b[0] = *(const uint32_t*)(rfs + br * 72 + ks * 16 + 2 * c);
            b[1] = *(const uint32_t*)(rfs + br * 72 + ks * 16 + 8 + 2 * c);
            mma_f16(acc[t], a, b);
        }
    }

    float mx0 = -3.0e38f, mx1 = -3.0e38f;
#pragma unroll
    for (int t = 0; t < 34; ++t) {
        int c0 = t * 8 + 2 * c;
        if (c0 < 266)     { mx0 = fmaxf(mx0, acc[t][0]); mx1 = fmaxf(mx1, acc[t][2]); }
        if (c0 + 1 < 266) { mx0 = fmaxf(mx0, acc[t][1]); mx1 = fmaxf(mx1, acc[t][3]); }
    }
    mx0 = fmaxf(mx0, __shfl_xor_sync(0xffffffffu, mx0, 1));
    mx0 = fmaxf(mx0, __shfl_xor_sync(0xffffffffu, mx0, 2));
    mx1 = fmaxf(mx1, __shfl_xor_sync(0xffffffffu, mx1, 1));
    mx1 = fmaxf(mx1, __shfl_xor_sync(0xffffffffu, mx1, 2));

    int b0i = row0 >> 16, rem0 = row0 & 65535, l0 = rem0 >> 4, hh0 = rem0 & 15;
    int b1i = row1 >> 16, rem1 = row1 & 65535, l1 = rem1 >> 4, hh1 = rem1 & 15;
    __half* d0p = out + ((size_t)(b0i * 16 + hh0) * LL + l0) * MP;
    __half* d1p = out + ((size_t)(b1i * 16 + hh1) * LL + l1) * MP;

#pragma unroll
    for (int t = 0; t < 34; ++t) {
        int c0 = t * 8 + 2 * c;
        float v0x = (c0     < 266) ? __expf(h0 + acc[t][0] - mx0) * PHI_SCALE : 0.f;
        float v0y = (c0 + 1 < 266) ? __expf(h0 + acc[t][1] - mx0) * PHI_SCALE : 0.f;
        float v1x = (c0     < 266) ? __expf(h1 + acc[t][2] - mx1) * PHI_SCALE : 0.f;
        float v1y = (c0 + 1 < 266) ? __expf(h1 + acc[t][3] - mx1) * PHI_SCALE : 0.f;
        *(__half2*)&d0p[c0] = __floats2half2_rn(v0x, v0y);
        *(__half2*)&d1p[c0] = __floats2half2_rn(v1x, v1y);
    }
}

// ---------------- kv as FP16 MMA: kvT[d][m] = sum_l vT[d][l]*kp[l][m] ----------
__global__ __launch_bounds__(256) void kv_gemm_kernel(float* __restrict__ kvpart)
{
    __shared__ __align__(16) __half kps[32 * 280];
    __shared__ __align__(16) __half vsT[80 * 40];

    int tid = threadIdx.x;
    int lane = tid & 31, w = tid >> 5;
    int split = blockIdx.x, bh = blockIdx.y;
    int b = bh >> 4, h = bh & 15;
    int c = lane & 3, r = lane >> 2;

    for (int idx = tid; idx < 16 * 40; idx += 256) {
        int rr = idx / 40, l = idx % 40;
        vsT[(64 + rr) * 40 + l] = (rr == 0) ? __float2half(1.0f)
                                            : __ushort_as_half((unsigned short)0);
    }

    int lrow_ldsm = (lane & 7) + ((lane & 8) ? 8 : 0);
    uint32_t kpsBase = (uint32_t)__cvta_generic_to_shared(kps) + 2 * (lrow_ldsm * 280);

    int ntiles = (w < 2) ? 5 : 4;
    float acc[5][5][4];
#pragma unroll
    for (int mt = 0; mt < 5; ++mt)
#pragma unroll
        for (int j = 0; j < 5; ++j)
#pragma unroll
            for (int i = 0; i < 4; ++i) acc[mt][j][i] = 0.f;

    int lbase = split * 1024;
    for (int ch = 0; ch < 32; ++ch) {
        int l0 = lbase + ch * 32;
        __syncthreads();
        for (int idx = tid; idx < 32 * 34; idx += 256) {
            int l = idx / 34, m8 = idx % 34;
            *(float4*)&kps[l * 280 + m8 * 8] =
                *(const float4*)&g_kp[((size_t)bh * LL + l0 + l) * MP + m8 * 8];
        }
        for (int idx = tid; idx < 32 * 32; idx += 256) {
            int l = idx >> 5, d2 = idx & 31;
            __half2 v = *(const __half2*)&g_vprojh[((size_t)(b * LL + l0 + l)) * DD + h * DH + 2 * d2];
            vsT[(2 * d2 + 0) * 40 + l] = __low2half(v);
            vsT[(2 * d2 + 1) * 40 + l] = __high2half(v);
        }
        __syncthreads();

#pragma unroll
        for (int ks = 0; ks < 2; ++ks) {
            uint32_t a[5][4];
#pragma unroll
            for (int mt = 0; mt < 5; ++mt) {
                int ar = mt * 16 + r;
                a[mt][0] = *(const uint32_t*)(vsT + ar * 40 + ks * 16 + 2 * c);
                a[mt][1] = *(const uint32_t*)(vsT + (ar + 8) * 40 + ks * 16 + 2 * c);
                a[mt][2] = *(const uint32_t*)(vsT + ar * 40 + ks * 16 + 8 + 2 * c);
                a[mt][3] = *(const uint32_t*)(vsT + (ar + 8) * 40 + ks * 16 + 8 + 2 * c);
            }
#pragma unroll
            for (int j = 0; j < 5; ++j) {
                if (j >= ntiles) break;
                int t = (j < 4) ? (w + 8 * j) : (32 + w);
                uint32_t bfr[2];
                ldsm_x2_t(bfr, kpsBase + 2 * (ks * 16 * 280 + t * 8));
#pragma unroll
                for (int mt = 0; mt < 5; ++mt)
                    mma_f16(acc[mt][j], a[mt], bfr);
            }
        }
    }

    float* dst = kvpart + (size_t)(split * 64 + bh) * 80 * 272;
#pragma unroll
    for (int mt = 0; mt < 5; ++mt) {
        int d0 = mt * 16 + r;
#pragma unroll
        for (int j = 0; j < 5; ++j) {
            if (j >= ntiles) break;
            int t = (j < 4) ? (w + 8 * j) : (32 + w);
            int cc = t * 8 + 2 * c;
            *(float2*)&dst[d0 * 272 + cc]       = make_float2(acc[mt][j][0], acc[mt][j][1]);
            *(float2*)&dst[(d0 + 8) * 272 + cc] = make_float2(acc[mt][j][2], acc[mt][j][3]);
        }
    }
}

__global__ __launch_bounds__(256) void kv_reduce_kernel(
    const float* __restrict__ kvpart)
{
    int idx = blockIdx.x * 256 + threadIdx.x;
    const int total = 64 * 80 * 272;
    if (idx < total) {
        float s = kvpart[idx] + kvpart[total + idx]
                + kvpart[2 * total + idx] + kvpart[3 * total + idx];
        g_kvT[idx] = __float2half_rn(s);
    }
}

// ---------------- ctx as FP16 MMA with fused denom -> fp16 out ------------------
__global__ __launch_bounds__(256) void ctx_gemm_kernel()
{
    extern __shared__ __align__(16) __half csm[];
    __half* kvs = csm;               // [80][280]
    __half* As  = csm + 80 * 280;    // [128][24]

    int tid = threadIdx.x;
    int lane = tid & 31, w = tid >> 5;
    int bh = blockIdx.y;
    int b = bh >> 4, h = bh & 15;
    int lblk = blockIdx.x * 128;
    int c = lane & 3, r = lane >> 2;

    for (int idx = tid; idx < 80 * 34; idx += 256) {
        int d = idx / 34, q = idx % 34;
        *(float4*)&kvs[d * 280 + q * 8] =
            *(const float4*)&g_kvT[(size_t)bh * 80 * 272 + d * 272 + q * 8];
    }

    float acc[9][4];
#pragma unroll
    for (int t = 0; t < 9; ++t)
#pragma unroll
        for (int i = 0; i < 4; ++i) acc[t][i] = 0.f;

    int arow = w * 16 + r;

    for (int ch = 0; ch < 17; ++ch) {
        __syncthreads();
        {
            int rr = tid >> 1, part = tid & 1;
            *(float4*)&As[rr * 24 + part * 8] =
                *(const float4*)&g_qp[((size_t)bh * LL + lblk + rr) * MP + ch * 16 + part * 8];
        }
        __syncthreads();

        uint32_t a[4];
        a[0] = *(const uint32_t*)(As + arow * 24 + 2 * c);
        a[1] = *(const uint32_t*)(As + (arow + 8) * 24 + 2 * c);
        a[2] = *(const uint32_t*)(As + arow * 24 + 8 + 2 * c);
        a[3] = *(const uint32_t*)(As + (arow + 8) * 24 + 8 + 2 * c);
#pragma unroll
        for (int t = 0; t < 9; ++t) {
            int br = t * 8 + r;
            uint32_t bfr[2];
            bfr[0] = *(const uint32_t*)(kvs + br * 280 + ch * 16 + 2 * c);
            bfr[1] = *(const uint32_t*)(kvs + br * 280 + ch * 16 + 8 + 2 * c);
            mma_f16(acc[t], a, bfr);
        }
    }

    float den0 = __shfl_sync(0xffffffffu, acc[8][0], lane & ~3);
    float den1 = __shfl_sync(0xffffffffu, acc[8][2], lane & ~3);
    float inv0 = 1.0f / (den0 + 1e-6f);
    float inv1 = 1.0f / (den1 + 1e-6f);

    int lrow0 = lblk + arow, lrow1 = lblk + arow + 8;
    __half* o0 = g_ctxh + ((size_t)(b * LL + lrow0)) * DD + h * DH;
    __half* o1 = g_ctxh + ((size_t)(b * LL + lrow1)) * DD + h * DH;
#pragma unroll
    for (int t = 0; t < 8; ++t) {
        int cc = t * 8 + 2 * c;
        *(__half2*)&o0[cc] = __floats2half2_rn(acc[t][0] * inv0, acc[t][1] * inv0);
        *(__half2*)&o1[cc] = __floats2half2_rn(acc[t][2] * inv1, acc[t][3] * inv1);
    }
}

// ---------------- host launcher ------------------------------------------------
extern "C" void kernel_launch(void* const* d_in, const int* in_sizes, int n_in,
                              void* d_out, int out_size)
{
    const float* query = (const float*)d_in[0];
    const float* key   = (const float*)d_in[1];
    const float* value = (const float*)d_in[2];
    const float* q_w   = (const float*)d_in[3];
    const float* q_b   = (const float*)d_in[4];
    const float* k_w   = (const float*)d_in[5];
    const float* k_b   = (const float*)d_in[6];
    const float* v_w   = (const float*)d_in[7];
    const float* v_b   = (const float*)d_in[8];
    const float* out_w = (const float*)d_in[9];
    const float* out_b = (const float*)d_in[10];
    const float* rf    = (const float*)d_in[11];
    float* out = (float*)d_out;

    float* p_kvpart;
    cudaGetSymbolAddress((void**)&p_kvpart, g_kvpart);

    int gemm_smem = 4 * 128 * SHH * sizeof(__half);            // 73,728 B
    int phi_smem  = 272 * 72 * sizeof(__half);                 // 39,168 B
    int ctx_smem  = (80 * 280 + 128 * 24) * sizeof(__half);    // 50,944 B
    cudaFuncSetAttribute(gemm_proj_kernel, cudaFuncAttributeMaxDynamicSharedMemorySize, gemm_smem);
    cudaFuncSetAttribute(gemm_out_kernel,  cudaFuncAttributeMaxDynamicSharedMemorySize, gemm_smem);
    cudaFuncSetAttribute(phi_gemm_kernel,  cudaFuncAttributeMaxDynamicSharedMemorySize, phi_smem);
    cudaFuncSetAttribute(ctx_gemm_kernel,  cudaFuncAttributeMaxDynamicSharedMemorySize, ctx_smem);

    const int NB = NROWS * DD / 4;
    const int WB = DD * DD / 4;

    dim3 f3Grid((NB + 255) / 256, 3);
    f2h3_kernel<<<f3Grid, 256>>>((const float4*)query, (const float4*)key,
                                 (const float4*)value, NB);
    dim3 f4Grid((WB + 255) / 256, 4);
    f2h4_kernel<<<f4Grid, 256>>>((const float4*)q_w, (const float4*)k_w,
                                 (const float4*)v_w, (const float4*)out_w, WB);

    dim3 projGrid(DD / 128, NROWS / 128, 3);   // (8, 128, 3)
    gemm_proj_kernel<<<projGrid, 256, gemm_smem>>>(q_b, k_b, v_b);

    dim3 phiGrid(GROWS / 128, 2);              // (2048, 2)
    phi_gemm_kernel<<<phiGrid, 256, phi_smem>>>(rf);

    dim3 kvGrid(4, BB * HH);
    kv_gemm_kernel<<<kvGrid, 256>>>(p_kvpart);
    kv_reduce_kernel<<<(64 * 80 * 272 + 255) / 256, 256>>>(p_kvpart);

    dim3 ctxGrid(LL / 128, BB * HH);
    ctx_gemm_kernel<<<ctxGrid, 256, ctx_smem>>>();

    dim3 outGrid(DD / 128, NROWS / 128);
    gemm_out_kernel<<<outGrid, 256, gemm_smem>>>(out_b, out);
}